// round 3
// baseline (speedup 1.0000x reference)
#include <cuda_runtime.h>
#include <cuda_bf16.h>
#include <cstdint>

// Resample2d (FlowNet2 bilinear warp), fixed shapes:
//   input1 [B=4, C=64, H=384, W=512] fp32
//   input2 [B=4, 2,    H=384, W=512] fp32  (dx, dy)
//   out    [B=4, C=64, H=384, W=512] fp32
//
// SMEM-staged gathers (re-bench of R2 design after infra failure):
//   Block = 512 threads = one 8-row x 512-col output tile for 8 channels.
//   Thread t owns column t for all 8 rows; flow/weights computed ONCE into
//   registers. Per channel: stage a 17-row band (+/-4 halo) into SMEM with
//   coalesced float4 loads; gathers become LDS (~2-way conflicts) instead of
//   scattered LDG (10-18 L1 line-wavefronts each). Out-of-window pixels
//   (P ~ 6e-5 for N(0,1) flow) take an exact predicated global fallback.

#define RS_B 4
#define RS_C 64
#define RS_H 384
#define RS_W 512
#define RS_HW (RS_H * RS_W)
#define RS_CHW (RS_C * RS_HW)

#define TH 8            // output rows per tile
#define HALO 4          // rows of halo; window = TH + 1 + 2*HALO = 17
#define SROWS (TH + 1 + 2 * HALO)   // 17
#define CPG 8           // channels per block
#define NG (RS_C / CPG) // 8 groups

__global__ __launch_bounds__(512, 2) void resample2d_smem_kernel(
    const float* __restrict__ in1,
    const float* __restrict__ flow,
    float* __restrict__ out)
{
    __shared__ float tile[SROWS][RS_W];   // 34816 B

    const int tid  = threadIdx.x;         // 0..511 == column
    const int col  = tid;
    const int h0   = blockIdx.x * TH;     // tile top row
    const int b    = blockIdx.y;
    const int g    = blockIdx.z;          // channel group

    // ---- per-pixel params (8 rows, this column), computed once ----
    float alpha[TH], beta[TH];
    uint32_t pk[TH];                       // xL | xR<<9 | yT<<18 | dbit<<27 | ok<<28

    const float* flowb = flow + (size_t)b * 2 * RS_HW;
#pragma unroll
    for (int r = 0; r < TH; ++r) {
        const int h = h0 + r;
        const int t = h * RS_W + col;
        const float dx = flowb[t];
        const float dy = flowb[RS_HW + t];
        const float xf = (float)col + dx;
        const float yf = (float)h + dy;
        const float x0 = floorf(xf);
        const float y0 = floorf(yf);
        alpha[r] = xf - x0;
        beta[r]  = yf - y0;
        const int x0i = (int)x0;
        const int y0i = (int)y0;
        const int xL = min(max(x0i,     0), RS_W - 1);
        const int xR = min(max(x0i + 1, 0), RS_W - 1);
        const int yT = min(max(y0i,     0), RS_H - 1);
        const int yB = min(max(y0i + 1, 0), RS_H - 1);
        const int dbit = yB - yT;                      // 0 or 1
        const int sT = yT - (h0 - HALO);               // slot of top row
        const bool ok = (sT >= 0) && (sT + dbit <= SROWS - 1);
        pk[r] = (uint32_t)xL | ((uint32_t)xR << 9) | ((uint32_t)yT << 18)
              | ((uint32_t)dbit << 27) | (ok ? (1u << 28) : 0u);
    }

    const float* basec = in1 + (size_t)b * RS_CHW + (size_t)g * CPG * RS_HW;
    float*       outc  = out + (size_t)b * RS_CHW + (size_t)g * CPG * RS_HW;

    for (int ci = 0; ci < CPG; ++ci) {
        const float* src = basec + ci * RS_HW;

        __syncthreads();   // previous channel's reads done before restage
        // ---- stage 17-row band, coalesced float4; 2176 float4s / 512 thr ----
        {
            int r  = tid >> 7;            // 0..3
            int x4 = (tid & 127) << 2;    // float index 0..508
#pragma unroll
            for (int k = 0; k < 5; ++k) { // 5*512 = 2560 >= 2176 slots
                if (r < SROWS) {
                    const int gr = min(max(h0 - HALO + r, 0), RS_H - 1);
                    *(float4*)&tile[r][x4] =
                        *(const float4*)(src + gr * RS_W + x4);
                }
                r += 4;                   // 512 threads / 128 float4-per-row
            }
        }
        __syncthreads();

        float* outp = outc + ci * RS_HW;
#pragma unroll
        for (int r = 0; r < TH; ++r) {
            const uint32_t p = pk[r];
            const int xL   = (int)(p & 511u);
            const int xR   = (int)((p >> 9) & 511u);
            const int yT   = (int)((p >> 18) & 511u);
            const int dbit = (int)((p >> 27) & 1u);
            const float a  = alpha[r];
            const float bb = beta[r];

            float vTL, vTR, vBL, vBR;
            if (p & (1u << 28)) {
                const int sT = yT - (h0 - HALO);
                vTL = tile[sT][xL];
                vTR = tile[sT][xR];
                vBL = tile[sT + dbit][xL];
                vBR = tile[sT + dbit][xR];
            } else {
                const int yB = yT + dbit;
                vTL = __ldg(src + yT * RS_W + xL);
                vTR = __ldg(src + yT * RS_W + xR);
                vBL = __ldg(src + yB * RS_W + xL);
                vBR = __ldg(src + yB * RS_W + xR);
            }

            const float wTR = a * (1.0f - bb);
            const float wBL = (1.0f - a) * bb;
            const float wBR = a * bb;
            const float wTL = 1.0f - wTR - wBL - wBR;

            outp[(h0 + r) * RS_W + col] =
                fmaf(wTL, vTL, fmaf(wTR, vTR, fmaf(wBL, vBL, wBR * vBR)));
        }
    }
}

extern "C" void kernel_launch(void* const* d_in, const int* in_sizes, int n_in,
                              void* d_out, int out_size)
{
    const float* in1  = (const float*)d_in[0];
    const float* flow = (const float*)d_in[1];
    float* out = (float*)d_out;

    dim3 grid(RS_H / TH, RS_B, NG);   // 48 x 4 x 8 = 1536 blocks
    resample2d_smem_kernel<<<grid, 512>>>(in1, flow, out);
}

// round 5
// speedup vs baseline: 2.9190x; 2.9190x over previous
#include <cuda_runtime.h>
#include <cuda_bf16.h>
#include <cstdint>

// Resample2d (FlowNet2 bilinear warp), fixed shapes:
//   input1 [B=4, C=64, H=384, W=512] fp32
//   input2 [B=4, 2,    H=384, W=512] fp32  (dx, dy)
//   out    [B=4, C=64, H=384, W=512] fp32
//
// R5 = re-bench of R4 (infra failure, not a kernel verdict).
// Direct-gather design; L/R taps of each sample row merged into one aligned
// LDG.64 at e = xL & ~1 (xR is always xL or xL+1). Odd-xL lanes issue one
// extra predicated scalar load per row for TR. Gather L1 accesses per
// (pixel,channel): 4 -> ~3 effective. Occupancy 6 CTAs/SM.

#define RS_B 4
#define RS_C 64
#define RS_H 384
#define RS_W 512
#define RS_HW (RS_H * RS_W)
#define RS_CHW (RS_C * RS_HW)

__global__ __launch_bounds__(256, 6) void resample2d_kernel(
    const float* __restrict__ in1,   // [B,C,H,W]
    const float* __restrict__ flow,  // [B,2,H,W]
    float* __restrict__ out)         // [B,C,H,W]
{
    const int t = blockIdx.x * 256 + threadIdx.x;   // pixel index h*W+w
    const int b = blockIdx.y;
    if (t >= RS_HW) return;

    const int w = t & (RS_W - 1);
    const int h = t >> 9;                            // W = 512 = 2^9

    const float* flowb = flow + b * 2 * RS_HW;
    const float dx = flowb[t];
    const float dy = flowb[RS_HW + t];

    const float xf = (float)w + dx;
    const float yf = (float)h + dy;
    const float x0 = floorf(xf);
    const float y0 = floorf(yf);
    const float alpha = xf - x0;
    const float beta  = yf - y0;

    const int x0i = (int)x0;
    const int y0i = (int)y0;
    const int xL = min(max(x0i,     0), RS_W - 1);
    const int xR = min(max(x0i + 1, 0), RS_W - 1);
    const int yT = min(max(y0i,     0), RS_H - 1);
    const int yB = min(max(y0i + 1, 0), RS_H - 1);

    const float wTR = alpha * (1.0f - beta);
    const float wBL = (1.0f - alpha) * beta;
    const float wBR = alpha * beta;
    const float wTL = 1.0f - wTR - wBL - wBR;

    const int e = xL & ~1;                    // even base of the L/R pair
    const bool lo = (xL & 1) != 0;            // TL sits in .y of the pair
    const bool pairHasR = (!lo) || (xR == xL); // TR available in pair?
    // Extra-load column: xR when needed; harmless in-bounds addr otherwise.
    const int xX = pairHasR ? xL : xR;
    const int oT = yT * RS_W;
    const int oB = yB * RS_W;

    const float* base = in1 + b * RS_CHW;
    float* outp = out + b * RS_CHW + t;

#pragma unroll 4
    for (int c = 0; c < RS_C; ++c) {
        const float* p = base + c * RS_HW;

        const float2 aT = __ldg((const float2*)(p + oT + e));
        const float2 aB = __ldg((const float2*)(p + oB + e));
        float vTR_x = 0.0f, vBR_x = 0.0f;
        if (!pairHasR) {                     // ~50% of lanes, predicated
            vTR_x = __ldg(p + oT + xX);
            vBR_x = __ldg(p + oB + xX);
        }

        const float vTL = lo ? aT.y : aT.x;
        const float vBL = lo ? aB.y : aB.x;
        float vTR, vBR;
        if (xR == xL)      { vTR = vTL;   vBR = vBL;   }
        else if (!lo)      { vTR = aT.y;  vBR = aB.y;  }
        else               { vTR = vTR_x; vBR = vBR_x; }

        outp[c * RS_HW] = fmaf(wTL, vTL,
                          fmaf(wTR, vTR,
                          fmaf(wBL, vBL,
                               wBR * vBR)));
    }
}

extern "C" void kernel_launch(void* const* d_in, const int* in_sizes, int n_in,
                              void* d_out, int out_size)
{
    const float* in1  = (const float*)d_in[0];
    const float* flow = (const float*)d_in[1];
    float* out = (float*)d_out;

    dim3 grid(RS_HW / 256, RS_B);   // 768 x 4 = 3072 blocks
    resample2d_kernel<<<grid, 256>>>(in1, flow, out);
}